// round 2
// baseline (speedup 1.0000x reference)
#include <cuda_runtime.h>

// HyperNetResidualV2: B=2048, D=256
// out = xin + (relu(bn2(relu(bn1(xin)) @ W1 + b1)) @ W2 + b2)
// Fully fused: one CTA (256 thr) per sample; activations live in SMEM.
// HBM-stream bound on w1/w2 (2 x 512 MB read once => ~1.07 GB total).
// Roofline floor ~134 us @ 8 TB/s.

#define DIM 256
#define BN_EPS 1e-3f

__device__ __forceinline__ float4 ldcs_f4(const float4* p) {
    // streaming load: weights are touched exactly once
    return __ldcs(p);
}

__global__ __launch_bounds__(256)
void hypernet_fused_kernel(
    const float* __restrict__ xin,
    const float* __restrict__ w1,
    const float* __restrict__ b1,
    const float* __restrict__ w2,
    const float* __restrict__ b2,
    const float* __restrict__ gamma1, const float* __restrict__ beta1,
    const float* __restrict__ mean1,  const float* __restrict__ var1,
    const float* __restrict__ gamma2, const float* __restrict__ beta2,
    const float* __restrict__ mean2,  const float* __restrict__ var2,
    float* __restrict__ out)
{
    __shared__ float xin_s[DIM];          // residual stash
    __shared__ float h[DIM];              // activation vector (reused for both blocks)
    __shared__ float4 part[4 * 64];       // 4 d-slices x 64 float4 partials (= 4 x 256 floats)

    const int b  = blockIdx.x;
    const int t  = threadIdx.x;           // 0..255
    const int eq = t & 63;                // output quad index: e = 4*eq .. 4*eq+3
    const int ds = t >> 6;                // d-slice 0..3, covers d in [ds*64, ds*64+64)
    const int dbase = ds * 64;

    // ---- BN1 + ReLU (one element per thread) ----
    const float x0 = xin[b * DIM + t];
    xin_s[t] = x0;
    {
        const float s  = gamma1[t] * rsqrtf(var1[t] + BN_EPS);
        const float sh = beta1[t] - mean1[t] * s;
        h[t] = fmaxf(fmaf(x0, s, sh), 0.0f);
    }
    __syncthreads();

    // ---- matvec 1: y[e] = sum_d h[d] * W1[b, d, e] ----
    {
        const float4* __restrict__ W =
            reinterpret_cast<const float4*>(w1 + (size_t)b * DIM * DIM);
        float4 acc = make_float4(0.f, 0.f, 0.f, 0.f);
        #pragma unroll 8
        for (int i = 0; i < 64; i++) {
            const int d = dbase + i;
            const float  hv = h[d];              // warp-uniform broadcast from SMEM
            const float4 w  = ldcs_f4(&W[d * 64 + eq]);  // LDG.128 streaming, coalesced
            acc.x = fmaf(hv, w.x, acc.x);
            acc.y = fmaf(hv, w.y, acc.y);
            acc.z = fmaf(hv, w.z, acc.z);
            acc.w = fmaf(hv, w.w, acc.w);
        }
        part[ds * 64 + eq] = acc;                // STS.128, conflict-free
    }
    __syncthreads();

    // ---- reduce partials, add b1, BN2 + ReLU ----
    {
        const float* pf = reinterpret_cast<const float*>(part);
        const float y = pf[0 * DIM + t] + pf[1 * DIM + t]
                      + pf[2 * DIM + t] + pf[3 * DIM + t]
                      + b1[b * DIM + t];
        const float s  = gamma2[t] * rsqrtf(var2[t] + BN_EPS);
        const float sh = beta2[t] - mean2[t] * s;
        h[t] = fmaxf(fmaf(y, s, sh), 0.0f);      // safe: all reads of h (matvec1) done pre-sync
    }
    __syncthreads();

    // ---- matvec 2 ----
    {
        const float4* __restrict__ W =
            reinterpret_cast<const float4*>(w2 + (size_t)b * DIM * DIM);
        float4 acc = make_float4(0.f, 0.f, 0.f, 0.f);
        #pragma unroll 8
        for (int i = 0; i < 64; i++) {
            const int d = dbase + i;
            const float  hv = h[d];
            const float4 w  = ldcs_f4(&W[d * 64 + eq]);
            acc.x = fmaf(hv, w.x, acc.x);
            acc.y = fmaf(hv, w.y, acc.y);
            acc.z = fmaf(hv, w.z, acc.z);
            acc.w = fmaf(hv, w.w, acc.w);
        }
        part[ds * 64 + eq] = acc;
    }
    __syncthreads();

    // ---- reduce, add b2, residual, store ----
    {
        const float* pf = reinterpret_cast<const float*>(part);
        const float y2 = pf[0 * DIM + t] + pf[1 * DIM + t]
                       + pf[2 * DIM + t] + pf[3 * DIM + t]
                       + b2[b * DIM + t];
        out[b * DIM + t] = xin_s[t] + y2;
    }
}

extern "C" void kernel_launch(void* const* d_in, const int* in_sizes, int n_in,
                              void* d_out, int out_size)
{
    const float* xin    = (const float*)d_in[0];
    const float* w1     = (const float*)d_in[1];
    const float* b1     = (const float*)d_in[2];
    const float* w2     = (const float*)d_in[3];
    const float* b2     = (const float*)d_in[4];
    const float* gamma1 = (const float*)d_in[5];
    const float* beta1  = (const float*)d_in[6];
    const float* mean1  = (const float*)d_in[7];
    const float* var1   = (const float*)d_in[8];
    const float* gamma2 = (const float*)d_in[9];
    const float* beta2  = (const float*)d_in[10];
    const float* mean2  = (const float*)d_in[11];
    const float* var2   = (const float*)d_in[12];
    float* out = (float*)d_out;

    const int B = in_sizes[0] / DIM;   // 2048

    hypernet_fused_kernel<<<B, DIM>>>(
        xin, w1, b1, w2, b2,
        gamma1, beta1, mean1, var1,
        gamma2, beta2, mean2, var2,
        out);
}